// round 1
// baseline (speedup 1.0000x reference)
#include <cuda_runtime.h>

#define BNUM  32
#define TENC  4096
#define TPRED 1024
#define DHALF 512      // floats per half-feature (E = P = 512)
#define DFULL 1024
#define NCLS  4
#define ENC_TS  16     // t-splits for enc  (4096/256)
#define PRED_TS 8      // t-splits for pred (1024/128)
#define TCH_E 256
#define TCH_P 128
#define LN_EPS 1e-5f

// Scratch (no allocations allowed in kernel_launch)
__device__ float g_part_e[ENC_TS  * BNUM * NCLS * DHALF];  // 4 MB
__device__ float g_part_p[PRED_TS * BNUM * NCLS * DHALF];  // 2 MB
__device__ int   g_cnt_e[BNUM * NCLS];
__device__ int   g_cnt_p[BNUM * NCLS];
__device__ float g_loss_b[BNUM];

// ---------------------------------------------------------------------------
// Per-(b, tensor) class histogram
// grid (BNUM, 2), 256 threads
// ---------------------------------------------------------------------------
__global__ void count_kernel(const int* __restrict__ lab_e,
                             const int* __restrict__ lab_p) {
    __shared__ int h[NCLS];
    int b = blockIdx.x;
    bool enc = (blockIdx.y == 0);
    int T = enc ? TENC : TPRED;
    const int* L = (enc ? lab_e : lab_p) + (size_t)b * T;
    if (threadIdx.x < NCLS) h[threadIdx.x] = 0;
    __syncthreads();
    for (int i = threadIdx.x; i < T; i += blockDim.x)
        atomicAdd(&h[L[i]], 1);
    __syncthreads();
    if (threadIdx.x < NCLS) {
        int* dst = enc ? g_cnt_e : g_cnt_p;
        dst[b * NCLS + threadIdx.x] = h[threadIdx.x];
    }
}

// ---------------------------------------------------------------------------
// Masked partial sums. grid (tsplits, BNUM), 128 threads.
// Each thread owns 4 consecutive d (float4) of the 512-wide row and keeps
// 4 class accumulators. Branch-free predicated accumulation so ptxas can
// batch the LDG.128s (MLP ~ unroll factor).
// which: 0 = enc (writes g_part_e), 1 = pred (writes g_part_p)
// ---------------------------------------------------------------------------
__global__ void masked_sum_kernel(const float4* __restrict__ x,
                                  const int*    __restrict__ lab,
                                  int T, int tchunk, int which) {
    int ts  = blockIdx.x;
    int b   = blockIdx.y;
    int tid = threadIdx.x;               // 0..127
    int t0  = ts * tchunk;

    extern __shared__ int slab[];        // tchunk labels
    for (int i = tid; i < tchunk; i += 128)
        slab[i] = lab[(size_t)b * T + t0 + i];
    __syncthreads();

    const float4* xp = x + ((size_t)b * T + t0) * (DHALF / 4) + tid;

    float4 a0 = {0.f,0.f,0.f,0.f};
    float4 a1 = {0.f,0.f,0.f,0.f};
    float4 a2 = {0.f,0.f,0.f,0.f};
    float4 a3 = {0.f,0.f,0.f,0.f};

    #pragma unroll 8
    for (int t = 0; t < tchunk; ++t) {
        float4 v = xp[(size_t)t * (DHALF / 4)];
        int c = slab[t];
        a0.x += (c == 0) ? v.x : 0.f;  a0.y += (c == 0) ? v.y : 0.f;
        a0.z += (c == 0) ? v.z : 0.f;  a0.w += (c == 0) ? v.w : 0.f;
        a1.x += (c == 1) ? v.x : 0.f;  a1.y += (c == 1) ? v.y : 0.f;
        a1.z += (c == 1) ? v.z : 0.f;  a1.w += (c == 1) ? v.w : 0.f;
        a2.x += (c == 2) ? v.x : 0.f;  a2.y += (c == 2) ? v.y : 0.f;
        a2.z += (c == 2) ? v.z : 0.f;  a2.w += (c == 2) ? v.w : 0.f;
        a3.x += (c == 3) ? v.x : 0.f;  a3.y += (c == 3) ? v.y : 0.f;
        a3.z += (c == 3) ? v.z : 0.f;  a3.w += (c == 3) ? v.w : 0.f;
    }

    float4* pp = (float4*)(which ? g_part_p : g_part_e);
    size_t base = (((size_t)ts * BNUM + b) * NCLS) * (DHALF / 4) + tid;
    pp[base + 0 * (DHALF / 4)] = a0;
    pp[base + 1 * (DHALF / 4)] = a1;
    pp[base + 2 * (DHALF / 4)] = a2;
    pp[base + 3 * (DHALF / 4)] = a3;
}

// ---------------------------------------------------------------------------
// Per-b finalize: reduce partials -> means -> LN -> 4x4 logits -> log-softmax
// diagonal (via label indices) -> per-b loss contribution.
// grid BNUM, 256 threads. Threads 0..127 own enc half (d<512), 128..255 pred.
// Each thread handles 4 consecutive d for all 4 classes.
// ---------------------------------------------------------------------------
__global__ void finalize_b(const int*   __restrict__ label,
                           const float* __restrict__ norm_w,
                           const float* __restrict__ norm_b,
                           const float* __restrict__ head_w,
                           const float* __restrict__ head_b) {
    int b    = blockIdx.x;
    int tid  = threadIdx.x;
    int lane = tid & 31;
    int wid  = tid >> 5;                 // 0..7
    bool is_enc = (tid < 128);
    int dl = (tid & 127) * 4;            // local float index within half
    int gd = is_enc ? dl : (DHALF + dl); // global d within 1024

    float4 f[NCLS];
    #pragma unroll
    for (int c = 0; c < NCLS; ++c) {
        float4 acc = {0.f,0.f,0.f,0.f};
        if (is_enc) {
            size_t base = ((size_t)b * NCLS + c) * (DHALF / 4) + (dl >> 2);
            #pragma unroll
            for (int ts = 0; ts < ENC_TS; ++ts) {
                float4 v = ((const float4*)g_part_e)[(size_t)ts * BNUM * NCLS * (DHALF / 4) + base];
                acc.x += v.x; acc.y += v.y; acc.z += v.z; acc.w += v.w;
            }
            float inv = 1.f / fmaxf((float)g_cnt_e[b * NCLS + c], 1.f);
            acc.x *= inv; acc.y *= inv; acc.z *= inv; acc.w *= inv;
        } else {
            size_t base = ((size_t)b * NCLS + c) * (DHALF / 4) + (dl >> 2);
            #pragma unroll
            for (int ts = 0; ts < PRED_TS; ++ts) {
                float4 v = ((const float4*)g_part_p)[(size_t)ts * BNUM * NCLS * (DHALF / 4) + base];
                acc.x += v.x; acc.y += v.y; acc.z += v.z; acc.w += v.w;
            }
            float inv = 1.f / fmaxf((float)g_cnt_p[b * NCLS + c], 1.f);
            acc.x *= inv; acc.y *= inv; acc.z *= inv; acc.w *= inv;
        }
        f[c] = acc;
    }

    // LayerNorm statistics per class over 1024 values
    __shared__ float s_red[2 * NCLS][8];
    __shared__ float s_mu[NCLS], s_rstd[NCLS];
    #pragma unroll
    for (int c = 0; c < NCLS; ++c) {
        float s = f[c].x + f[c].y + f[c].z + f[c].w;
        float q = f[c].x*f[c].x + f[c].y*f[c].y + f[c].z*f[c].z + f[c].w*f[c].w;
        #pragma unroll
        for (int o = 16; o; o >>= 1) {
            s += __shfl_xor_sync(0xffffffffu, s, o);
            q += __shfl_xor_sync(0xffffffffu, q, o);
        }
        if (lane == 0) { s_red[c * 2][wid] = s; s_red[c * 2 + 1][wid] = q; }
    }
    __syncthreads();
    if (tid < NCLS) {
        float s = 0.f, q = 0.f;
        #pragma unroll
        for (int w = 0; w < 8; ++w) { s += s_red[tid * 2][w]; q += s_red[tid * 2 + 1][w]; }
        float mu  = s / (float)DFULL;
        float var = q / (float)DFULL - mu * mu;
        s_mu[tid]   = mu;
        s_rstd[tid] = rsqrtf(var + LN_EPS);
    }
    __syncthreads();

    // Normalize + partial logits
    float4 w4 = *(const float4*)(norm_w + gd);
    float4 b4 = *(const float4*)(norm_b + gd);
    float4 hw[NCLS];
    #pragma unroll
    for (int n = 0; n < NCLS; ++n)
        hw[n] = *(const float4*)(head_w + (size_t)n * DFULL + gd);

    float pl[NCLS][NCLS];   // [c][n]
    #pragma unroll
    for (int c = 0; c < NCLS; ++c) {
        float mu = s_mu[c], r = s_rstd[c];
        float fx = (f[c].x - mu) * r * w4.x + b4.x;
        float fy = (f[c].y - mu) * r * w4.y + b4.y;
        float fz = (f[c].z - mu) * r * w4.z + b4.z;
        float fw = (f[c].w - mu) * r * w4.w + b4.w;
        #pragma unroll
        for (int n = 0; n < NCLS; ++n)
            pl[c][n] = fx * hw[n].x + fy * hw[n].y + fz * hw[n].z + fw * hw[n].w;
    }

    __shared__ float s_lg[8][NCLS][NCLS];
    #pragma unroll
    for (int c = 0; c < NCLS; ++c)
        #pragma unroll
        for (int n = 0; n < NCLS; ++n) {
            float v = pl[c][n];
            #pragma unroll
            for (int o = 16; o; o >>= 1)
                v += __shfl_xor_sync(0xffffffffu, v, o);
            if (lane == 0) s_lg[wid][c][n] = v;
        }
    __syncthreads();

    __shared__ float s_logits[NCLS][NCLS];
    if (tid < NCLS * NCLS) {
        int c = tid >> 2, n = tid & 3;
        float v = 0.f;
        #pragma unroll
        for (int w = 0; w < 8; ++w) v += s_lg[w][c][n];
        s_logits[c][n] = v + head_b[n];
    }
    __syncthreads();

    if (tid == 0) {
        float sel_sum = 0.f;
        #pragma unroll
        for (int l = 0; l < NCLS; ++l) {
            int lb = label[b * NCLS + l];
            float m = s_logits[lb][0];
            #pragma unroll
            for (int n = 1; n < NCLS; ++n) m = fmaxf(m, s_logits[lb][n]);
            float se = 0.f;
            #pragma unroll
            for (int n = 0; n < NCLS; ++n) se += expf(s_logits[lb][n] - m);
            sel_sum += s_logits[lb][lb] - m - logf(se);
        }
        g_loss_b[b] = sel_sum;
    }
}

// ---------------------------------------------------------------------------
// Final scalar
// ---------------------------------------------------------------------------
__global__ void reduce_loss(float* __restrict__ out) {
    float v = g_loss_b[threadIdx.x];   // 32 threads
    #pragma unroll
    for (int o = 16; o; o >>= 1)
        v += __shfl_xor_sync(0xffffffffu, v, o);
    if (threadIdx.x == 0)
        out[0] = -v / (float)(BNUM * NCLS);
}

// ---------------------------------------------------------------------------
extern "C" void kernel_launch(void* const* d_in, const int* in_sizes, int n_in,
                              void* d_out, int out_size) {
    const float* enc_out = (const float*)d_in[0];
    const float* pred_out = (const float*)d_in[1];
    const int*   frame_label  = (const int*)d_in[2];
    const int*   frame_tlabel = (const int*)d_in[3];
    const int*   label  = (const int*)d_in[4];
    const float* norm_w = (const float*)d_in[5];
    const float* norm_b = (const float*)d_in[6];
    const float* head_w = (const float*)d_in[7];
    const float* head_b = (const float*)d_in[8];
    float* out = (float*)d_out;

    count_kernel<<<dim3(BNUM, 2), 256>>>(frame_label, frame_tlabel);

    masked_sum_kernel<<<dim3(ENC_TS, BNUM), 128, TCH_E * sizeof(int)>>>(
        (const float4*)enc_out, frame_label, TENC, TCH_E, 0);
    masked_sum_kernel<<<dim3(PRED_TS, BNUM), 128, TCH_P * sizeof(int)>>>(
        (const float4*)pred_out, frame_tlabel, TPRED, TCH_P, 1);

    finalize_b<<<BNUM, 256>>>(label, norm_w, norm_b, head_w, head_b);
    reduce_loss<<<1, 32>>>(out);
}

// round 2
// speedup vs baseline: 1.6142x; 1.6142x over previous
#include <cuda_runtime.h>

#define BNUM  32
#define TENC  4096
#define TPRED 1024
#define DHALF 512      // floats per half-feature (E = P = 512)
#define DFULL 1024
#define NCLS  4
#define ENC_TS  32     // 4096 / 128
#define PRED_TS 8      // 1024 / 128
#define TCHUNK  128
#define LN_EPS 1e-5f

// Scratch (no allocations allowed)
__device__ float g_part_e[ENC_TS  * BNUM * NCLS * DHALF];  // 8 MB
__device__ float g_part_p[PRED_TS * BNUM * NCLS * DHALF];  // 2 MB
__device__ float g_mean[BNUM * NCLS * DFULL];              // 512 KB
__device__ float g_loss_b[BNUM];

// ---------------------------------------------------------------------------
// Merged masked partial sums (enc + pred in one launch, uniform CTA work).
// grid (ENC_TS + PRED_TS, BNUM), 128 threads. Each block: 128 rows x 512 d.
// Thread owns one float4 column slice; 4 class accumulators, predicated adds.
// ---------------------------------------------------------------------------
__global__ void __launch_bounds__(128)
masked_sum_kernel(const float4* __restrict__ enc,
                  const float4* __restrict__ pred,
                  const int*    __restrict__ lab_e,
                  const int*    __restrict__ lab_p) {
    int ts  = blockIdx.x;
    int b   = blockIdx.y;
    int tid = threadIdx.x;

    const float4* x;
    const int*    lab;
    float4*       pp;
    int T, tsl;
    if (ts < ENC_TS) {
        x = enc;  lab = lab_e; pp = (float4*)g_part_e; T = TENC;  tsl = ts;
    } else {
        x = pred; lab = lab_p; pp = (float4*)g_part_p; T = TPRED; tsl = ts - ENC_TS;
    }
    int t0 = tsl * TCHUNK;

    __shared__ int slab[TCHUNK];
    slab[tid] = lab[(size_t)b * T + t0 + tid];
    __syncthreads();

    const float4* xp = x + ((size_t)b * T + t0) * (DHALF / 4) + tid;

    float4 a0 = {0.f,0.f,0.f,0.f};
    float4 a1 = {0.f,0.f,0.f,0.f};
    float4 a2 = {0.f,0.f,0.f,0.f};
    float4 a3 = {0.f,0.f,0.f,0.f};

    #pragma unroll 8
    for (int t = 0; t < TCHUNK; ++t) {
        float4 v = __ldcs(&xp[(size_t)t * (DHALF / 4)]);
        int c = slab[t];
        a0.x += (c == 0) ? v.x : 0.f;  a0.y += (c == 0) ? v.y : 0.f;
        a0.z += (c == 0) ? v.z : 0.f;  a0.w += (c == 0) ? v.w : 0.f;
        a1.x += (c == 1) ? v.x : 0.f;  a1.y += (c == 1) ? v.y : 0.f;
        a1.z += (c == 1) ? v.z : 0.f;  a1.w += (c == 1) ? v.w : 0.f;
        a2.x += (c == 2) ? v.x : 0.f;  a2.y += (c == 2) ? v.y : 0.f;
        a2.z += (c == 2) ? v.z : 0.f;  a2.w += (c == 2) ? v.w : 0.f;
        a3.x += (c == 3) ? v.x : 0.f;  a3.y += (c == 3) ? v.y : 0.f;
        a3.z += (c == 3) ? v.z : 0.f;  a3.w += (c == 3) ? v.w : 0.f;
    }

    size_t base = (((size_t)tsl * BNUM + b) * NCLS) * (DHALF / 4) + tid;
    pp[base + 0 * (DHALF / 4)] = a0;
    pp[base + 1 * (DHALF / 4)] = a1;
    pp[base + 2 * (DHALF / 4)] = a2;
    pp[base + 3 * (DHALF / 4)] = a3;
}

// ---------------------------------------------------------------------------
// Reduce partials over t-splits + compute class counts inline -> g_mean.
// grid (NCLS, BNUM, 2), 128 threads.  z: 0 = enc, 1 = pred.
// ---------------------------------------------------------------------------
__global__ void __launch_bounds__(128)
reduce_mean_kernel(const int* __restrict__ lab_e,
                   const int* __restrict__ lab_p) {
    int c   = blockIdx.x;
    int b   = blockIdx.y;
    int wch = blockIdx.z;
    int tid = threadIdx.x;
    int lane = tid & 31, wid = tid >> 5;

    const int*   lab;
    const float* part;
    int T, S;
    if (wch == 0) { lab = lab_e; part = g_part_e; T = TENC;  S = ENC_TS;  }
    else          { lab = lab_p; part = g_part_p; T = TPRED; S = PRED_TS; }

    // inline class count
    int cnt = 0;
    for (int i = tid; i < T; i += 128)
        cnt += (lab[(size_t)b * T + i] == c);
    #pragma unroll
    for (int o = 16; o; o >>= 1)
        cnt += __shfl_xor_sync(0xffffffffu, cnt, o);
    __shared__ int scnt[4];
    __shared__ float s_inv;
    if (lane == 0) scnt[wid] = cnt;
    __syncthreads();
    if (tid == 0) {
        int tot = scnt[0] + scnt[1] + scnt[2] + scnt[3];
        s_inv = 1.f / fmaxf((float)tot, 1.f);
    }
    __syncthreads();

    // reduce splits for my float4 slice
    float4 acc = {0.f,0.f,0.f,0.f};
    size_t base = ((size_t)b * NCLS + c) * (DHALF / 4) + tid;
    size_t stride = (size_t)BNUM * NCLS * (DHALF / 4);
    for (int s = 0; s < S; ++s) {
        float4 v = ((const float4*)part)[(size_t)s * stride + base];
        acc.x += v.x; acc.y += v.y; acc.z += v.z; acc.w += v.w;
    }
    float inv = s_inv;
    acc.x *= inv; acc.y *= inv; acc.z *= inv; acc.w *= inv;

    float4* dst = (float4*)(g_mean + ((size_t)b * NCLS + c) * DFULL + wch * DHALF);
    dst[tid] = acc;
}

// ---------------------------------------------------------------------------
// Per-b finalize: g_mean -> LN -> 4x4 logits -> log-softmax diag -> loss_b.
// grid BNUM, 256 threads. Threads 0..127 enc half, 128..255 pred half.
// ---------------------------------------------------------------------------
__global__ void __launch_bounds__(256)
finalize_b(const int*   __restrict__ label,
           const float* __restrict__ norm_w,
           const float* __restrict__ norm_b,
           const float* __restrict__ head_w,
           const float* __restrict__ head_b) {
    int b    = blockIdx.x;
    int tid  = threadIdx.x;
    int lane = tid & 31;
    int wid  = tid >> 5;                 // 0..7
    int gd   = tid * 4;                  // global d within 1024

    float4 f[NCLS];
    #pragma unroll
    for (int c = 0; c < NCLS; ++c)
        f[c] = *(const float4*)(g_mean + ((size_t)b * NCLS + c) * DFULL + gd);

    // LayerNorm statistics per class over 1024 values
    __shared__ float s_red[2 * NCLS][8];
    __shared__ float s_mu[NCLS], s_rstd[NCLS];
    #pragma unroll
    for (int c = 0; c < NCLS; ++c) {
        float s = f[c].x + f[c].y + f[c].z + f[c].w;
        float q = f[c].x*f[c].x + f[c].y*f[c].y + f[c].z*f[c].z + f[c].w*f[c].w;
        #pragma unroll
        for (int o = 16; o; o >>= 1) {
            s += __shfl_xor_sync(0xffffffffu, s, o);
            q += __shfl_xor_sync(0xffffffffu, q, o);
        }
        if (lane == 0) { s_red[c * 2][wid] = s; s_red[c * 2 + 1][wid] = q; }
    }
    __syncthreads();
    if (tid < NCLS) {
        float s = 0.f, q = 0.f;
        #pragma unroll
        for (int w = 0; w < 8; ++w) { s += s_red[tid * 2][w]; q += s_red[tid * 2 + 1][w]; }
        float mu  = s / (float)DFULL;
        float var = q / (float)DFULL - mu * mu;
        s_mu[tid]   = mu;
        s_rstd[tid] = rsqrtf(var + LN_EPS);
    }
    __syncthreads();

    // Normalize + partial logits
    float4 w4 = *(const float4*)(norm_w + gd);
    float4 b4 = *(const float4*)(norm_b + gd);
    float4 hw[NCLS];
    #pragma unroll
    for (int n = 0; n < NCLS; ++n)
        hw[n] = *(const float4*)(head_w + (size_t)n * DFULL + gd);

    float pl[NCLS][NCLS];   // [c][n]
    #pragma unroll
    for (int c = 0; c < NCLS; ++c) {
        float mu = s_mu[c], r = s_rstd[c];
        float fx = (f[c].x - mu) * r * w4.x + b4.x;
        float fy = (f[c].y - mu) * r * w4.y + b4.y;
        float fz = (f[c].z - mu) * r * w4.z + b4.z;
        float fw = (f[c].w - mu) * r * w4.w + b4.w;
        #pragma unroll
        for (int n = 0; n < NCLS; ++n)
            pl[c][n] = fx * hw[n].x + fy * hw[n].y + fz * hw[n].z + fw * hw[n].w;
    }

    __shared__ float s_lg[8][NCLS][NCLS];
    #pragma unroll
    for (int c = 0; c < NCLS; ++c)
        #pragma unroll
        for (int n = 0; n < NCLS; ++n) {
            float v = pl[c][n];
            #pragma unroll
            for (int o = 16; o; o >>= 1)
                v += __shfl_xor_sync(0xffffffffu, v, o);
            if (lane == 0) s_lg[wid][c][n] = v;
        }
    __syncthreads();

    __shared__ float s_logits[NCLS][NCLS];
    if (tid < NCLS * NCLS) {
        int c = tid >> 2, n = tid & 3;
        float v = 0.f;
        #pragma unroll
        for (int w = 0; w < 8; ++w) v += s_lg[w][c][n];
        s_logits[c][n] = v + head_b[n];
    }
    __syncthreads();

    if (tid == 0) {
        float sel_sum = 0.f;
        #pragma unroll
        for (int l = 0; l < NCLS; ++l) {
            int lb = label[b * NCLS + l];
            float m = s_logits[lb][0];
            #pragma unroll
            for (int n = 1; n < NCLS; ++n) m = fmaxf(m, s_logits[lb][n]);
            float se = 0.f;
            #pragma unroll
            for (int n = 0; n < NCLS; ++n) se += expf(s_logits[lb][n] - m);
            sel_sum += s_logits[lb][lb] - m - logf(se);
        }
        g_loss_b[b] = sel_sum;
    }
}

// ---------------------------------------------------------------------------
__global__ void reduce_loss(float* __restrict__ out) {
    float v = g_loss_b[threadIdx.x];   // 32 threads
    #pragma unroll
    for (int o = 16; o; o >>= 1)
        v += __shfl_xor_sync(0xffffffffu, v, o);
    if (threadIdx.x == 0)
        out[0] = -v / (float)(BNUM * NCLS);
}

// ---------------------------------------------------------------------------
extern "C" void kernel_launch(void* const* d_in, const int* in_sizes, int n_in,
                              void* d_out, int out_size) {
    const float* enc_out = (const float*)d_in[0];
    const float* pred_out = (const float*)d_in[1];
    const int*   frame_label  = (const int*)d_in[2];
    const int*   frame_tlabel = (const int*)d_in[3];
    const int*   label  = (const int*)d_in[4];
    const float* norm_w = (const float*)d_in[5];
    const float* norm_b = (const float*)d_in[6];
    const float* head_w = (const float*)d_in[7];
    const float* head_b = (const float*)d_in[8];
    float* out = (float*)d_out;

    masked_sum_kernel<<<dim3(ENC_TS + PRED_TS, BNUM), 128>>>(
        (const float4*)enc_out, (const float4*)pred_out,
        frame_label, frame_tlabel);

    reduce_mean_kernel<<<dim3(NCLS, BNUM, 2), 128>>>(frame_label, frame_tlabel);

    finalize_b<<<BNUM, 256>>>(label, norm_w, norm_b, head_w, head_b);
    reduce_loss<<<1, 32>>>(out);
}

// round 3
// speedup vs baseline: 1.6307x; 1.0102x over previous
#include <cuda_runtime.h>

#define BNUM  32
#define TENC  4096
#define TPRED 1024
#define DHALF 512
#define DFULL 1024
#define NCLS  4
#define ENC_TS  32     // 4096 / 128
#define PRED_TS 8      // 1024 / 128
#define TCHUNK  128
#define LN_EPS 1e-5f

__device__ float g_part_e[ENC_TS  * BNUM * NCLS * DHALF];  // 8 MB
__device__ float g_part_p[PRED_TS * BNUM * NCLS * DHALF];  // 2 MB
__device__ float g_loss_b[BNUM];
__device__ unsigned int g_ticket = 0;

// ---------------------------------------------------------------------------
// Merged masked partial sums (enc + pred, uniform CTA work).
// grid (ENC_TS + PRED_TS, BNUM), 128 threads.
// ---------------------------------------------------------------------------
__global__ void __launch_bounds__(128)
masked_sum_kernel(const float4* __restrict__ enc,
                  const float4* __restrict__ pred,
                  const int*    __restrict__ lab_e,
                  const int*    __restrict__ lab_p) {
    int ts  = blockIdx.x;
    int b   = blockIdx.y;
    int tid = threadIdx.x;

    const float4* x;
    const int*    lab;
    float4*       pp;
    int T, tsl;
    if (ts < ENC_TS) {
        x = enc;  lab = lab_e; pp = (float4*)g_part_e; T = TENC;  tsl = ts;
    } else {
        x = pred; lab = lab_p; pp = (float4*)g_part_p; T = TPRED; tsl = ts - ENC_TS;
    }
    int t0 = tsl * TCHUNK;

    __shared__ int slab[TCHUNK];
    slab[tid] = lab[(size_t)b * T + t0 + tid];
    __syncthreads();

    const float4* xp = x + ((size_t)b * T + t0) * (DHALF / 4) + tid;

    float4 a0 = {0.f,0.f,0.f,0.f};
    float4 a1 = {0.f,0.f,0.f,0.f};
    float4 a2 = {0.f,0.f,0.f,0.f};
    float4 a3 = {0.f,0.f,0.f,0.f};

    #pragma unroll 8
    for (int t = 0; t < TCHUNK; ++t) {
        float4 v = __ldcs(&xp[(size_t)t * (DHALF / 4)]);
        int c = slab[t];
        a0.x += (c == 0) ? v.x : 0.f;  a0.y += (c == 0) ? v.y : 0.f;
        a0.z += (c == 0) ? v.z : 0.f;  a0.w += (c == 0) ? v.w : 0.f;
        a1.x += (c == 1) ? v.x : 0.f;  a1.y += (c == 1) ? v.y : 0.f;
        a1.z += (c == 1) ? v.z : 0.f;  a1.w += (c == 1) ? v.w : 0.f;
        a2.x += (c == 2) ? v.x : 0.f;  a2.y += (c == 2) ? v.y : 0.f;
        a2.z += (c == 2) ? v.z : 0.f;  a2.w += (c == 2) ? v.w : 0.f;
        a3.x += (c == 3) ? v.x : 0.f;  a3.y += (c == 3) ? v.y : 0.f;
        a3.z += (c == 3) ? v.z : 0.f;  a3.w += (c == 3) ? v.w : 0.f;
    }

    size_t base = (((size_t)tsl * BNUM + b) * NCLS) * (DHALF / 4) + tid;
    pp[base + 0 * (DHALF / 4)] = a0;
    pp[base + 1 * (DHALF / 4)] = a1;
    pp[base + 2 * (DHALF / 4)] = a2;
    pp[base + 3 * (DHALF / 4)] = a3;
}

// ---------------------------------------------------------------------------
// Fused tail: per-b partial reduction + counts + LN + logits + loss,
// last-block ticket writes the scalar. grid BNUM, 1024 threads.
// Thread mapping for reduction: c = tid>>8, h = (tid>>7)&1, d4 = tid&127.
// ---------------------------------------------------------------------------
__global__ void __launch_bounds__(1024)
tail_kernel(const int*   __restrict__ lab_e,
            const int*   __restrict__ lab_p,
            const int*   __restrict__ label,
            const float* __restrict__ norm_w,
            const float* __restrict__ norm_b,
            const float* __restrict__ head_w,
            const float* __restrict__ head_b,
            float*       __restrict__ out) {
    int b    = blockIdx.x;
    int tid  = threadIdx.x;
    int lane = tid & 31;
    int wid  = tid >> 5;                 // 0..31

    __shared__ float s_feat[NCLS][DFULL];        // means, 16 KB
    __shared__ int   s_cw[2][32][NCLS];          // per-warp counts
    __shared__ float s_inv[2][NCLS];

    // ---- class counts (enc: 4 ints/thread, pred: 1 int/thread) ----
    int ce[NCLS] = {0,0,0,0};
    int cp[NCLS] = {0,0,0,0};
    #pragma unroll
    for (int i = 0; i < 4; ++i) {
        int v = lab_e[(size_t)b * TENC + tid * 4 + i];
        ce[0] += (v == 0); ce[1] += (v == 1); ce[2] += (v == 2); ce[3] += (v == 3);
    }
    {
        int v = lab_p[(size_t)b * TPRED + tid];
        cp[0] += (v == 0); cp[1] += (v == 1); cp[2] += (v == 2); cp[3] += (v == 3);
    }
    #pragma unroll
    for (int k = 0; k < NCLS; ++k) {
        #pragma unroll
        for (int o = 16; o; o >>= 1) {
            ce[k] += __shfl_xor_sync(0xffffffffu, ce[k], o);
            cp[k] += __shfl_xor_sync(0xffffffffu, cp[k], o);
        }
        if (lane == 0) { s_cw[0][wid][k] = ce[k]; s_cw[1][wid][k] = cp[k]; }
    }
    __syncthreads();
    if (tid < 2 * NCLS) {
        int h = tid >> 2, k = tid & 3;
        int tot = 0;
        #pragma unroll
        for (int w = 0; w < 32; ++w) tot += s_cw[h][w][k];
        s_inv[h][k] = 1.f / fmaxf((float)tot, 1.f);
    }
    __syncthreads();

    // ---- reduce partials over t-splits -> means into smem ----
    {
        int c  = tid >> 8;
        int h  = (tid >> 7) & 1;
        int d4 = tid & 127;
        const float4* part;
        int S;
        if (h == 0) { part = (const float4*)g_part_e; S = ENC_TS; }
        else        { part = (const float4*)g_part_p; S = PRED_TS; }
        size_t stride = (size_t)BNUM * NCLS * (DHALF / 4);
        size_t base   = ((size_t)b * NCLS + c) * (DHALF / 4) + d4;
        float4 acc = {0.f,0.f,0.f,0.f};
        #pragma unroll 8
        for (int s = 0; s < S; ++s) {
            float4 v = part[(size_t)s * stride + base];
            acc.x += v.x; acc.y += v.y; acc.z += v.z; acc.w += v.w;
        }
        float inv = s_inv[h][c];
        acc.x *= inv; acc.y *= inv; acc.z *= inv; acc.w *= inv;
        *(float4*)&s_feat[c][h * DHALF + d4 * 4] = acc;
    }
    __syncthreads();

    // ---- LayerNorm stats + logits (threads 0..255, 8 warps) ----
    __shared__ float s_red[2 * NCLS][8];
    __shared__ float s_mu[NCLS], s_rstd[NCLS];
    __shared__ float s_lg[8][NCLS][NCLS];
    __shared__ float s_logits[NCLS][NCLS];

    float4 f[NCLS];
    int gd = (tid & 255) * 4;
    if (tid < 256) {
        #pragma unroll
        for (int c = 0; c < NCLS; ++c) {
            f[c] = *(const float4*)&s_feat[c][gd];
            float s = f[c].x + f[c].y + f[c].z + f[c].w;
            float q = f[c].x*f[c].x + f[c].y*f[c].y + f[c].z*f[c].z + f[c].w*f[c].w;
            #pragma unroll
            for (int o = 16; o; o >>= 1) {
                s += __shfl_xor_sync(0xffffffffu, s, o);
                q += __shfl_xor_sync(0xffffffffu, q, o);
            }
            if (lane == 0) { s_red[c * 2][wid] = s; s_red[c * 2 + 1][wid] = q; }
        }
    }
    __syncthreads();
    if (tid < NCLS) {
        float s = 0.f, q = 0.f;
        #pragma unroll
        for (int w = 0; w < 8; ++w) { s += s_red[tid * 2][w]; q += s_red[tid * 2 + 1][w]; }
        float mu  = s / (float)DFULL;
        float var = q / (float)DFULL - mu * mu;
        s_mu[tid]   = mu;
        s_rstd[tid] = rsqrtf(var + LN_EPS);
    }
    __syncthreads();

    if (tid < 256) {
        float4 w4 = *(const float4*)(norm_w + gd);
        float4 b4 = *(const float4*)(norm_b + gd);
        float4 hw[NCLS];
        #pragma unroll
        for (int n = 0; n < NCLS; ++n)
            hw[n] = *(const float4*)(head_w + (size_t)n * DFULL + gd);

        #pragma unroll
        for (int c = 0; c < NCLS; ++c) {
            float mu = s_mu[c], r = s_rstd[c];
            float fx = (f[c].x - mu) * r * w4.x + b4.x;
            float fy = (f[c].y - mu) * r * w4.y + b4.y;
            float fz = (f[c].z - mu) * r * w4.z + b4.z;
            float fw = (f[c].w - mu) * r * w4.w + b4.w;
            #pragma unroll
            for (int n = 0; n < NCLS; ++n) {
                float v = fx * hw[n].x + fy * hw[n].y + fz * hw[n].z + fw * hw[n].w;
                #pragma unroll
                for (int o = 16; o; o >>= 1)
                    v += __shfl_xor_sync(0xffffffffu, v, o);
                if (lane == 0) s_lg[wid][c][n] = v;
            }
        }
    }
    __syncthreads();
    if (tid < NCLS * NCLS) {
        int c = tid >> 2, n = tid & 3;
        float v = 0.f;
        #pragma unroll
        for (int w = 0; w < 8; ++w) v += s_lg[w][c][n];
        s_logits[c][n] = v + head_b[n];
    }
    __syncthreads();

    // ---- per-b loss, last-block scalar reduce ----
    if (tid == 0) {
        float sel_sum = 0.f;
        #pragma unroll
        for (int l = 0; l < NCLS; ++l) {
            int lb = label[b * NCLS + l];
            float m = s_logits[lb][0];
            #pragma unroll
            for (int n = 1; n < NCLS; ++n) m = fmaxf(m, s_logits[lb][n]);
            float se = 0.f;
            #pragma unroll
            for (int n = 0; n < NCLS; ++n) se += expf(s_logits[lb][n] - m);
            sel_sum += s_logits[lb][lb] - m - logf(se);
        }
        g_loss_b[b] = sel_sum;
        __threadfence();
        unsigned int t = atomicAdd(&g_ticket, 1u);
        if (t == BNUM - 1) {
            float tot = 0.f;
            #pragma unroll
            for (int i = 0; i < BNUM; ++i) tot += g_loss_b[i];
            out[0] = -tot / (float)(BNUM * NCLS);
            g_ticket = 0;   // reset for next graph replay
        }
    }
}

// ---------------------------------------------------------------------------
extern "C" void kernel_launch(void* const* d_in, const int* in_sizes, int n_in,
                              void* d_out, int out_size) {
    const float* enc_out = (const float*)d_in[0];
    const float* pred_out = (const float*)d_in[1];
    const int*   frame_label  = (const int*)d_in[2];
    const int*   frame_tlabel = (const int*)d_in[3];
    const int*   label  = (const int*)d_in[4];
    const float* norm_w = (const float*)d_in[5];
    const float* norm_b = (const float*)d_in[6];
    const float* head_w = (const float*)d_in[7];
    const float* head_b = (const float*)d_in[8];
    float* out = (float*)d_out;

    masked_sum_kernel<<<dim3(ENC_TS + PRED_TS, BNUM), 128>>>(
        (const float4*)enc_out, (const float4*)pred_out,
        frame_label, frame_tlabel);

    tail_kernel<<<BNUM, 1024>>>(frame_label, frame_tlabel, label,
                                norm_w, norm_b, head_w, head_b, out);
}